// round 9
// baseline (speedup 1.0000x reference)
#include <cuda_runtime.h>
#include <math.h>
#include <float.h>
#include <limits.h>

#define NB     32
#define NM     10000
#define ND     512
#define KTOP   5
#define RV     32768          // 32*32*32 voxels per slot
#define RV4    8192           // in float4
#define BM     64             // m-tile per block
#define KC     64             // k-chunk (== per-z slice)
#define KP     68             // smem row pad: 272B stride -> conflict-free LDS.128
#define KSPLIT 8              // 512 / KC

// ---- device scratch ----
__device__ float g_part[KSPLIT * NB * NM];   // partial dot [z][b][m]
__device__ float g_kq[KSPLIT * NM];          // partial ||k||^2 [z][m]
__device__ int   g_topidx[NB * KTOP];

// ---------------- kernel 1: sim partials ----------------
// Grid (157, 8). Block 256 thr = 8 warps; tile 64 m x 32 b x 64 k.
// Warp w: b-group (w>>1)*8, m-half (w&1)*32. Thread: 1 m x 8 b, scalar FFMA.
// All inner-loop smem addresses are base + immediate (fully unrolled).
__global__ __launch_bounds__(256) void sim_stage(const float* __restrict__ x,
                                                 const float* __restrict__ keys) {
    __shared__ float ks[BM * KP];     // keys chunk [64 m][KP]  (17.4 KB)
    __shared__ float xs[NB * KP];     // x chunk    [32 b][KP]  ( 8.7 KB)

    const int tid  = threadIdx.x;
    const int m0   = blockIdx.x * BM;
    const int z    = blockIdx.y;
    const int k0_4 = z * (KC / 4);
    const int w    = tid >> 5, lane = tid & 31;
    const int b0   = (w >> 1) * 8;
    const int m_l  = ((w & 1) << 5) | lane;   // 0..63
    const int gm   = m0 + m_l;

    // fill ks: 64 rows x 16 float4 = 1024, 4 per thread (coalesced, read-once)
    {
        const float4* kg = reinterpret_cast<const float4*>(keys);
#pragma unroll
        for (int t = 0; t < 4; ++t) {
            int idx = tid + t * 256;
            int row = idx >> 4, c4 = idx & 15;
            int gr  = m0 + row;
            float4 v = make_float4(0.f, 0.f, 0.f, 0.f);
            if (gr < NM) v = __ldcs(kg + gr * (ND / 4) + k0_4 + c4);
            *reinterpret_cast<float4*>(ks + row * KP + c4 * 4) = v;
        }
    }
    // fill xs: 32 rows x 16 float4 = 512, 2 per thread
    {
        const float4* xg = reinterpret_cast<const float4*>(x);
#pragma unroll
        for (int t = 0; t < 2; ++t) {
            int idx = tid + t * 256;
            int row = idx >> 4, c4 = idx & 15;
            *reinterpret_cast<float4*>(xs + row * KP + c4 * 4) =
                xg[row * (ND / 4) + k0_4 + c4];
        }
    }
    __syncthreads();

    float acc[8] = {};
    const float* kr = ks + m_l * KP;          // thread's key row (conflict-free)
    const float* xr = xs + b0 * KP;           // warp's b-group base (broadcast)

    // hot loop: per kk = 1 LDS.128 ka + 8 broadcast LDS.128 xa + 32 FFMA
#pragma unroll
    for (int kk = 0; kk < KC / 4; ++kk) {
        float4 ka = *reinterpret_cast<const float4*>(kr + kk * 4);
#pragma unroll
        for (int b = 0; b < 8; ++b) {
            float4 xa = *reinterpret_cast<const float4*>(xr + b * KP + kk * 4);
            float a = acc[b];
            a = fmaf(ka.x, xa.x, a);
            a = fmaf(ka.y, xa.y, a);
            a = fmaf(ka.z, xa.z, a);
            a = fmaf(ka.w, xa.w, a);
            acc[b] = a;
        }
    }

    // key norms: only warps 0/1 (each m covered once), separate cheap pass
    if (w < 2 && gm < NM) {
        float kq = 0.f;
#pragma unroll
        for (int kk = 0; kk < KC / 4; ++kk) {
            float4 ka = *reinterpret_cast<const float4*>(kr + kk * 4);
            kq = fmaf(ka.x, ka.x, kq);
            kq = fmaf(ka.y, ka.y, kq);
            kq = fmaf(ka.z, ka.z, kq);
            kq = fmaf(ka.w, ka.w, kq);
        }
        g_kq[z * NM + gm] = kq;
    }

    if (gm < NM) {
#pragma unroll
        for (int b = 0; b < 8; ++b)
            g_part[(z * NB + b0 + b) * NM + gm] = acc[b];
    }
}

// ---------------- kernel 2: x-norm + 8-way reduce + normalize + top-5 ----------------
// One 1024-thread block per b. Tie-break matches jax.lax.top_k.
__global__ __launch_bounds__(1024) void topk_fused(const float* __restrict__ x,
                                                   float* __restrict__ out,
                                                   long long out_size) {
    __shared__ float sv[1024 * KTOP];
    __shared__ int   si[1024 * KTOP];
    __shared__ float wv[32];
    __shared__ int   wi[32];
    __shared__ int   wp[32];
    __shared__ float s_invx;

    const int b = blockIdx.x, tid = threadIdx.x;
    const int lane = tid & 31, warp = tid >> 5;

    // warp 0 computes 1/||x_b||
    if (warp == 0) {
        const float4* x4 = reinterpret_cast<const float4*>(x) + b * (ND / 4);
        float s = 0.f;
#pragma unroll
        for (int t = 0; t < 4; ++t) {
            float4 v = x4[lane + t * 32];
            s += v.x * v.x + v.y * v.y + v.z * v.z + v.w * v.w;
        }
#pragma unroll
        for (int o = 16; o > 0; o >>= 1) s += __shfl_xor_sync(0xffffffffu, s, o);
        if (lane == 0) s_invx = 1.f / fmaxf(sqrtf(s), 1e-12f);
    }
    __syncthreads();
    const float invx = s_invx;

    float v[KTOP]; int ix[KTOP];
#pragma unroll
    for (int p = 0; p < KTOP; ++p) { v[p] = -FLT_MAX; ix[p] = INT_MAX; }

    for (int i = tid; i < NM; i += 1024) {
        float dot = 0.f, kq = 0.f;
#pragma unroll
        for (int z = 0; z < KSPLIT; ++z) {
            dot += g_part[(z * NB + b) * NM + i];
            kq  += g_kq[z * NM + i];
        }
        float val = dot * invx * (1.f / fmaxf(sqrtf(kq), 1e-12f));
        if (val > v[KTOP - 1]) {                 // ascending i -> ties keep lower idx
            v[KTOP - 1] = val; ix[KTOP - 1] = i;
#pragma unroll
            for (int q = KTOP - 1; q > 0; --q) {
                if (v[q] > v[q - 1]) {
                    float tv = v[q]; v[q] = v[q - 1]; v[q - 1] = tv;
                    int   ti = ix[q]; ix[q] = ix[q - 1]; ix[q - 1] = ti;
                }
            }
        }
    }
#pragma unroll
    for (int p = 0; p < KTOP; ++p) { sv[p * 1024 + tid] = v[p]; si[p * 1024 + tid] = ix[p]; }
    __syncthreads();

    for (int k = 0; k < KTOP; ++k) {
        float bv = -FLT_MAX; int bi = INT_MAX; int bp = -1;
#pragma unroll
        for (int t = 0; t < KTOP; ++t) {
            int j = t * 1024 + tid;
            float vv = sv[j]; int ii = si[j];
            if (vv > bv || (vv == bv && ii < bi)) { bv = vv; bi = ii; bp = j; }
        }
#pragma unroll
        for (int o = 16; o > 0; o >>= 1) {
            float ov = __shfl_down_sync(0xffffffffu, bv, o);
            int   oi = __shfl_down_sync(0xffffffffu, bi, o);
            int   op = __shfl_down_sync(0xffffffffu, bp, o);
            if (ov > bv || (ov == bv && oi < bi)) { bv = ov; bi = oi; bp = op; }
        }
        if (lane == 0) { wv[warp] = bv; wi[warp] = bi; wp[warp] = bp; }
        __syncthreads();
        if (tid == 0) {
            float fv = wv[0]; int fi = wi[0]; int fp = wp[0];
#pragma unroll
            for (int ww = 1; ww < 32; ++ww) {
                if (wv[ww] > fv || (wv[ww] == fv && wi[ww] < fi)) {
                    fv = wv[ww]; fi = wi[ww]; fp = wp[ww];
                }
            }
            g_topidx[b * KTOP + k] = fi;
            sv[fp] = -FLT_MAX;                   // mask winner
            const long long base = (long long)NB * KTOP * RV;
            if (out_size >= base + 2LL * NB * KTOP) {
                out[base + b * KTOP + k]             = (float)fi;
                out[base + NB * KTOP + b * KTOP + k] = fv;
            }
        }
        __syncthreads();
    }
}

// ---------------- kernel 3: gather (exact-fit, streaming hints) ----------------
// 1280 blocks x 256 thr x 4 float4 == 160 slots * 8192 float4 exactly.
__global__ __launch_bounds__(256) void gather_kernel(const float* __restrict__ mv,
                                                     float* __restrict__ out) {
    const int i0    = blockIdx.x * 256 + threadIdx.x;   // float4 index
    const int slot0 = i0 >> 13;                          // /8192
    const int off   = i0 & 8191;

    int idx[4];
#pragma unroll
    for (int j = 0; j < 4; ++j) idx[j] = g_topidx[slot0 + j * 40];

    const float4* src = reinterpret_cast<const float4*>(mv);
    float4*       dst = reinterpret_cast<float4*>(out);
    float4 r[4];
#pragma unroll
    for (int j = 0; j < 4; ++j) r[j] = __ldcs(src + (long long)idx[j] * RV4 + off);
#pragma unroll
    for (int j = 0; j < 4; ++j) __stcs(dst + (long long)(slot0 + j * 40) * RV4 + off, r[j]);
}

extern "C" void kernel_launch(void* const* d_in, const int* in_sizes, int n_in,
                              void* d_out, int out_size) {
    const float* x    = (const float*)d_in[0];
    const float* keys = (const float*)d_in[1];
    const float* mv   = (const float*)d_in[2];
    float* out = (float*)d_out;

    dim3 simgrid((NM + BM - 1) / BM, KSPLIT);
    sim_stage<<<simgrid, 256>>>(x, keys);
    topk_fused<<<NB, 1024>>>(x, out, (long long)out_size);
    gather_kernel<<<1280, 256>>>(mv, out);
}

// round 10
// speedup vs baseline: 1.0506x; 1.0506x over previous
#include <cuda_runtime.h>
#include <math.h>
#include <float.h>
#include <limits.h>

#define NB     32
#define NM     10000
#define ND     512
#define KTOP   5
#define RV     32768          // 32*32*32 voxels per slot
#define RV4    8192           // in float4
#define BM     128            // m-tile per block
#define KC     64             // k-chunk (== per-z slice)
#define KP     68             // smem row pad: 272B stride -> conflict-free LDS.128
#define KSPLIT 8              // 512 / KC
#define NCH    25             // topk chunks
#define CH     400            // NM / NCH

// ---- device scratch ----
__device__ float g_part[KSPLIT * NB * NM];     // partial dot [z][b][m]
__device__ float g_kq[KSPLIT * NM];            // partial ||k||^2 [z][m]
__device__ float g_cand_val[NB * NCH * KTOP];  // per-chunk top-5 values
__device__ int   g_cand_idx[NB * NCH * KTOP];
__device__ int   g_topidx[NB * KTOP];

// ---------------- kernel 1: sim partials ----------------
// Grid (79, 8). Block 128 thr = 4 warps; tile 128 m x 32 b x 64 k.
// Warp w owns b-group 8w. Thread: 4 m (lane+32j) x 8 b.
// Per warp-kk: 4 ka LDS.128 (conflict-free) + 8 xa LDS.128 (broadcast) = 48 wf / 4096 FMA.
__global__ __launch_bounds__(128) void sim_stage(const float* __restrict__ x,
                                                 const float* __restrict__ keys) {
    __shared__ float ks[BM * KP];     // keys chunk [128 m][KP]  (34.8 KB)
    __shared__ float xs[NB * KP];     // x chunk    [32 b][KP]   ( 8.7 KB)

    const int tid  = threadIdx.x;
    const int m0   = blockIdx.x * BM;
    const int z    = blockIdx.y;
    const int k0_4 = z * (KC / 4);
    const int w    = tid >> 5, lane = tid & 31;
    const int b0   = w * 8;

    // fill ks: 128 rows x 16 float4 = 2048, 16 per thread (coalesced, read-once)
    {
        const float4* kg = reinterpret_cast<const float4*>(keys);
#pragma unroll
        for (int t = 0; t < 16; ++t) {
            int idx = tid + t * 128;
            int row = idx >> 4, c4 = idx & 15;
            int gr  = m0 + row;
            float4 v = make_float4(0.f, 0.f, 0.f, 0.f);
            if (gr < NM) v = __ldcs(kg + gr * (ND / 4) + k0_4 + c4);
            *reinterpret_cast<float4*>(ks + row * KP + c4 * 4) = v;
        }
    }
    // fill xs: 32 rows x 16 float4 = 512, 4 per thread
    {
        const float4* xg = reinterpret_cast<const float4*>(x);
#pragma unroll
        for (int t = 0; t < 4; ++t) {
            int idx = tid + t * 128;
            int row = idx >> 4, c4 = idx & 15;
            *reinterpret_cast<float4*>(xs + row * KP + c4 * 4) =
                xg[row * (ND / 4) + k0_4 + c4];
        }
    }
    __syncthreads();

    float acc[4][8] = {};
    const float* xr = xs + b0 * KP;

    // hot loop
#pragma unroll
    for (int kk = 0; kk < KC / 4; ++kk) {
        float4 ka[4];
#pragma unroll
        for (int j = 0; j < 4; ++j)
            ka[j] = *reinterpret_cast<const float4*>(ks + (lane + j * 32) * KP + kk * 4);
#pragma unroll
        for (int b = 0; b < 8; ++b) {
            float4 xa = *reinterpret_cast<const float4*>(xr + b * KP + kk * 4);
#pragma unroll
            for (int j = 0; j < 4; ++j) {
                float a = acc[j][b];
                a = fmaf(ka[j].x, xa.x, a);
                a = fmaf(ka[j].y, xa.y, a);
                a = fmaf(ka[j].z, xa.z, a);
                a = fmaf(ka[j].w, xa.w, a);
                acc[j][b] = a;
            }
        }
    }

    // key norms: warp 0 covers all 128 m rows (4 per thread)
    if (w == 0) {
#pragma unroll
        for (int j = 0; j < 4; ++j) {
            int gm = m0 + lane + j * 32;
            if (gm < NM) {
                const float* kr = ks + (lane + j * 32) * KP;
                float kq = 0.f;
#pragma unroll
                for (int kk = 0; kk < KC / 4; ++kk) {
                    float4 ka = *reinterpret_cast<const float4*>(kr + kk * 4);
                    kq = fmaf(ka.x, ka.x, kq);
                    kq = fmaf(ka.y, ka.y, kq);
                    kq = fmaf(ka.z, ka.z, kq);
                    kq = fmaf(ka.w, ka.w, kq);
                }
                g_kq[z * NM + gm] = kq;
            }
        }
    }

#pragma unroll
    for (int j = 0; j < 4; ++j) {
        int gm = m0 + lane + j * 32;
        if (gm < NM) {
#pragma unroll
            for (int b = 0; b < 8; ++b)
                g_part[(z * NB + b0 + b) * NM + gm] = acc[j][b];
        }
    }
}

// ---------------- kernel 2a: reduce + normalize + per-chunk top-5 ----------------
// Grid (NCH, NB), 256 thr. Block (c, b) handles m in [c*CH, (c+1)*CH).
// Tie-break everywhere: equal value -> lower index.
__global__ __launch_bounds__(256) void topk_stage_a(const float* __restrict__ x) {
    __shared__ float vals[CH];
    __shared__ float sv[256];
    __shared__ int   si[256];
    __shared__ float s_invx;

    const int c = blockIdx.x, b = blockIdx.y;
    const int tid = threadIdx.x;
    const int mbase = c * CH;

    // warp 0: 1/||x_b||
    if (tid < 32) {
        const float4* x4 = reinterpret_cast<const float4*>(x) + b * (ND / 4);
        float s = 0.f;
#pragma unroll
        for (int t = 0; t < 4; ++t) {
            float4 v = x4[tid + t * 32];
            s += v.x * v.x + v.y * v.y + v.z * v.z + v.w * v.w;
        }
#pragma unroll
        for (int o = 16; o > 0; o >>= 1) s += __shfl_xor_sync(0xffffffffu, s, o);
        if (tid == 0) s_invx = 1.f / fmaxf(sqrtf(s), 1e-12f);
    }
    __syncthreads();
    const float invx = s_invx;

    // reduce z + normalize
    for (int i = tid; i < CH; i += 256) {
        int m = mbase + i;
        float dot = 0.f, kq = 0.f;
#pragma unroll
        for (int z = 0; z < KSPLIT; ++z) {
            dot += g_part[(z * NB + b) * NM + m];
            kq  += g_kq[z * NM + m];
        }
        vals[i] = dot * invx * (1.f / fmaxf(sqrtf(kq), 1e-12f));
    }
    __syncthreads();

    // 5 argmax rounds over CH entries
    for (int k = 0; k < KTOP; ++k) {
        float bv = -FLT_MAX; int bi = CH;
        for (int i = tid; i < CH; i += 256) {
            float vv = vals[i];
            if (vv > bv || (vv == bv && i < bi)) { bv = vv; bi = i; }
        }
        sv[tid] = bv; si[tid] = bi;
        __syncthreads();
        for (int s = 128; s > 0; s >>= 1) {
            if (tid < s) {
                float v2 = sv[tid + s]; int i2 = si[tid + s];
                if (v2 > sv[tid] || (v2 == sv[tid] && i2 < si[tid])) {
                    sv[tid] = v2; si[tid] = i2;
                }
            }
            __syncthreads();
        }
        if (tid == 0) {
            g_cand_val[(b * NCH + c) * KTOP + k] = sv[0];
            g_cand_idx[(b * NCH + c) * KTOP + k] = mbase + si[0];
            vals[si[0]] = -FLT_MAX;
        }
        __syncthreads();
    }
}

// ---------------- kernel 2b: final top-5 from 125 candidates ----------------
__global__ __launch_bounds__(128) void topk_stage_b(float* __restrict__ out,
                                                    long long out_size) {
    __shared__ float cv[NCH * KTOP];
    __shared__ int   ci[NCH * KTOP];
    __shared__ float sv[128];
    __shared__ int   si[128];
    __shared__ int   sp[128];

    const int b = blockIdx.x, tid = threadIdx.x;
    if (tid < NCH * KTOP) {
        cv[tid] = g_cand_val[b * NCH * KTOP + tid];
        ci[tid] = g_cand_idx[b * NCH * KTOP + tid];
    }
    __syncthreads();

    for (int k = 0; k < KTOP; ++k) {
        float bv = -FLT_MAX; int bi = INT_MAX; int bp = -1;
        if (tid < NCH * KTOP) {
            bv = cv[tid]; bi = ci[tid]; bp = tid;
        }
        sv[tid] = bv; si[tid] = bi; sp[tid] = bp;
        __syncthreads();
        for (int s = 64; s > 0; s >>= 1) {
            if (tid < s) {
                float v2 = sv[tid + s]; int i2 = si[tid + s];
                if (v2 > sv[tid] || (v2 == sv[tid] && i2 < si[tid])) {
                    sv[tid] = v2; si[tid] = i2; sp[tid] = sp[tid + s];
                }
            }
            __syncthreads();
        }
        if (tid == 0) {
            g_topidx[b * KTOP + k] = si[0];
            cv[sp[0]] = -FLT_MAX;                // mask winner
            const long long base = (long long)NB * KTOP * RV;
            if (out_size >= base + 2LL * NB * KTOP) {
                out[base + b * KTOP + k]             = (float)si[0];
                out[base + NB * KTOP + b * KTOP + k] = sv[0];
            }
        }
        __syncthreads();
    }
}

// ---------------- kernel 3: gather (exact-fit, streaming hints) ----------------
// 1280 blocks x 256 thr x 4 float4 == 160 slots * 8192 float4 exactly.
__global__ __launch_bounds__(256) void gather_kernel(const float* __restrict__ mv,
                                                     float* __restrict__ out) {
    const int i0    = blockIdx.x * 256 + threadIdx.x;   // float4 index
    const int slot0 = i0 >> 13;                          // /8192
    const int off   = i0 & 8191;

    int idx[4];
#pragma unroll
    for (int j = 0; j < 4; ++j) idx[j] = g_topidx[slot0 + j * 40];

    const float4* src = reinterpret_cast<const float4*>(mv);
    float4*       dst = reinterpret_cast<float4*>(out);
    float4 r[4];
#pragma unroll
    for (int j = 0; j < 4; ++j) r[j] = __ldcs(src + (long long)idx[j] * RV4 + off);
#pragma unroll
    for (int j = 0; j < 4; ++j) __stcs(dst + (long long)(slot0 + j * 40) * RV4 + off, r[j]);
}

extern "C" void kernel_launch(void* const* d_in, const int* in_sizes, int n_in,
                              void* d_out, int out_size) {
    const float* x    = (const float*)d_in[0];
    const float* keys = (const float*)d_in[1];
    const float* mv   = (const float*)d_in[2];
    float* out = (float*)d_out;

    dim3 simgrid((NM + BM - 1) / BM, KSPLIT);
    sim_stage<<<simgrid, 128>>>(x, keys);
    dim3 tka(NCH, NB);
    topk_stage_a<<<tka, 256>>>(x);
    topk_stage_b<<<NB, 128>>>(out, (long long)out_size);
    gather_kernel<<<1280, 256>>>(mv, out);
}